// round 1
// baseline (speedup 1.0000x reference)
#include <cuda_runtime.h>
#include <cstdint>
#include <cstddef>

#define BB 16
#define NN 458
#define DD 128
#define EE 42240

// ---------------------------------------------------------------------------
// Scratch (device globals; no allocation allowed)
// ---------------------------------------------------------------------------
__device__ float g_x  [BB * NN * DD];        // current node features (after layer update)
__device__ float g_u  [BB * NN * DD];        // x @ W_src
__device__ float g_v  [BB * NN * DD];        // x @ W_dst + b_msg
__device__ float g_agg[2 * BB * NN * DD];    // two partial agg buffers (s-split halves)

// ---------------------------------------------------------------------------
// uv kernel: u = x @ Wsrc ; v = x @ Wdst + b_msg     (rows = B*N, 16 rows/CTA)
// wl points at w_msg[l] (shape [384,128] row-major). Wsrc = rows 0..127,
// Wdst = rows 128..255.
// ---------------------------------------------------------------------------
__global__ __launch_bounds__(128) void uv_kernel(const float* __restrict__ xin,
                                                 const float* __restrict__ wl,
                                                 const float* __restrict__ bl)
{
    __shared__ float xs[16][128];
    const int t    = threadIdx.x;
    const int row0 = blockIdx.x * 16;

    // pick input: explicit pointer (layer 0) or g_x (later layers)
    const float* x = (xin != nullptr) ? xin : g_x;

    // load 16 rows of x into smem (float4, coalesced)
    {
        const float4* src = (const float4*)(x + (size_t)row0 * DD);
        float4* dst = (float4*)&xs[0][0];
        #pragma unroll
        for (int i = 0; i < 4; i++) dst[t + i * 128] = src[t + i * 128];
    }
    __syncthreads();

    float au[16], av[16];
    #pragma unroll
    for (int r = 0; r < 16; r++) { au[r] = 0.f; av[r] = 0.f; }

    #pragma unroll 4
    for (int k = 0; k < 128; k++) {
        const float wu = __ldg(wl + k * 128 + t);
        const float wv = __ldg(wl + (128 + k) * 128 + t);
        #pragma unroll
        for (int r = 0; r < 16; r++) {
            const float xv = xs[r][k];
            au[r] += xv * wu;
            av[r] += xv * wv;
        }
    }

    const float bias = bl[t];
    #pragma unroll
    for (int r = 0; r < 16; r++) {
        const size_t o = (size_t)(row0 + r) * DD + t;
        g_u[o] = au[r];
        g_v[o] = av[r] + bias;
    }
}

// ---------------------------------------------------------------------------
// edge kernel: for each (batch, bipartite block, 32-dst tile, s-half):
//   agg[d,:] += (1/n_src) * sum_s relu( (e(s,d) @ Wedge) + u[s] + v[d] )
// Fused GEMM + aggregation, Wedge (64KB) + V tile (16KB) resident in smem,
// edge tiles (2 src x 32 dst = 64 rows x 128) staged through smem.
// Grid = 16 batches * 2 splits * 13 tiles = 416 CTAs, 256 threads.
// ---------------------------------------------------------------------------
#define EDGE_SMEM_FLOATS (16384 + 4096 + 64 * 132 + 256)

__global__ __launch_bounds__(256) void edge_kernel(const float* __restrict__ edge_attr,
                                                   const float* __restrict__ wl)
{
    extern __shared__ float sm[];
    float* sW = sm;                 // [128][128] Wedge
    float* sV = sm + 16384;         // [32][128]  v rows for dst tile
    float* sA = sm + 16384 + 4096;  // [64][132]  edge tile (padded)
    float* sU = sA + 64 * 132;      // [2][128]   u rows for src chunk

    const int tid = threadIdx.x;
    const int bx  = blockIdx.x;
    const int b     = bx / 26;
    const int rem   = bx % 26;
    const int split = rem / 13;
    const int tt    = rem % 13;

    int lb, dtile;
    if      (tt < 4)  { lb = 0; dtile = tt;      }
    else if (tt < 8)  { lb = 1; dtile = tt - 4;  }
    else if (tt < 12) { lb = 2; dtile = tt - 8;  }
    else              { lb = 3; dtile = 0;       }

    const int nsrc_a[4] = {64, 128, 128, 128};
    const int ndst_a[4] = {128, 128, 128, 10};
    const int eb_a  [4] = {0, 8192, 24576, 40960};
    const int so_a  [4] = {0, 64, 192, 320};
    const int do_a  [4] = {64, 192, 320, 448};

    const int n_src = nsrc_a[lb];
    const int n_dst = ndst_a[lb];
    const int ebase = eb_a[lb];
    const int soff  = so_a[lb];
    const int doff  = do_a[lb];
    const int d0    = dtile * 32;

    const int s_begin = split * (n_src >> 1);
    const int s_end   = s_begin + (n_src >> 1);

    // --- load Wedge (rows 256..383 of w_msg[l]) into smem ---
    {
        const float4* wsrc = (const float4*)(wl + 256 * 128);
        float4* d4 = (float4*)sW;
        #pragma unroll
        for (int i = tid; i < 4096; i += 256) d4[i] = wsrc[i];
    }
    // --- load V tile into smem (0-fill masked dst) ---
    for (int i = tid; i < 4096; i += 256) {
        const int dl = i >> 7, c = i & 127;
        const int dg = d0 + dl;
        sV[i] = (dg < n_dst) ? g_v[((size_t)b * NN + doff + dg) * DD + c] : 0.f;
    }

    const int trow = tid >> 4;   // 0..15  -> dst pair (trow*2 + {0,1})
    const int tcol = tid & 15;   // 0..15  -> cols tcol*8 .. tcol*8+7
    const int col  = tcol * 8;

    float agg[2][8];
    #pragma unroll
    for (int d = 0; d < 2; d++)
        #pragma unroll
        for (int j = 0; j < 8; j++) agg[d][j] = 0.f;

    for (int s0 = s_begin; s0 < s_end; s0 += 2) {
        __syncthreads();   // previous iteration done reading sA/sU

        // stage edge tile: 64 rows (2 src x 32 dst) x 128 floats
        for (int i = tid; i < 2048; i += 256) {
            const int r  = i >> 5, c4 = i & 31;
            const int sl = r >> 5, dl = r & 31;
            const int dg = d0 + dl;
            float4 v4 = make_float4(0.f, 0.f, 0.f, 0.f);
            if (dg < n_dst) {
                const size_t e = (size_t)ebase + (size_t)(s0 + sl) * n_dst + dg;
                v4 = *(const float4*)(edge_attr + ((size_t)b * EE + e) * DD + c4 * 4);
            }
            *(float4*)(sA + r * 132 + c4 * 4) = v4;
        }
        // stage u rows for the 2 src
        {
            const int sl = tid >> 7, c = tid & 127;
            sU[tid] = g_u[((size_t)b * NN + soff + s0 + sl) * DD + c];
        }
        __syncthreads();

        float acc[2][2][8];
        #pragma unroll
        for (int s = 0; s < 2; s++)
            #pragma unroll
            for (int d = 0; d < 2; d++)
                #pragma unroll
                for (int j = 0; j < 8; j++) acc[s][d][j] = 0.f;

        #pragma unroll 2
        for (int k = 0; k < 128; k++) {
            const float4 b0 = *(const float4*)(sW + k * 128 + col);
            const float4 b1 = *(const float4*)(sW + k * 128 + col + 4);
            const float bv[8] = {b0.x, b0.y, b0.z, b0.w, b1.x, b1.y, b1.z, b1.w};
            float av[2][2];
            #pragma unroll
            for (int s = 0; s < 2; s++)
                #pragma unroll
                for (int d = 0; d < 2; d++)
                    av[s][d] = sA[(s * 32 + trow * 2 + d) * 132 + k];
            #pragma unroll
            for (int s = 0; s < 2; s++)
                #pragma unroll
                for (int d = 0; d < 2; d++)
                    #pragma unroll
                    for (int j = 0; j < 8; j++)
                        acc[s][d][j] += av[s][d] * bv[j];
        }

        // epilogue: relu(acc + u + v), accumulate over s into agg
        float vv[2][8];
        #pragma unroll
        for (int d = 0; d < 2; d++) {
            const float4 v0 = *(const float4*)(sV + (trow * 2 + d) * 128 + col);
            const float4 v1 = *(const float4*)(sV + (trow * 2 + d) * 128 + col + 4);
            vv[d][0] = v0.x; vv[d][1] = v0.y; vv[d][2] = v0.z; vv[d][3] = v0.w;
            vv[d][4] = v1.x; vv[d][5] = v1.y; vv[d][6] = v1.z; vv[d][7] = v1.w;
        }
        #pragma unroll
        for (int s = 0; s < 2; s++) {
            const float4 u0 = *(const float4*)(sU + s * 128 + col);
            const float4 u1 = *(const float4*)(sU + s * 128 + col + 4);
            const float uu[8] = {u0.x, u0.y, u0.z, u0.w, u1.x, u1.y, u1.z, u1.w};
            #pragma unroll
            for (int d = 0; d < 2; d++)
                #pragma unroll
                for (int j = 0; j < 8; j++) {
                    const float val = acc[s][d][j] + uu[j] + vv[d][j];
                    agg[d][j] += fmaxf(val, 0.f);
                }
        }
    }

    // store partial agg (scaled by 1/deg) into this split's buffer
    const float scale = 1.f / (float)n_src;
    float* aggbuf = g_agg + (size_t)split * (BB * NN * DD);
    #pragma unroll
    for (int d = 0; d < 2; d++) {
        const int dg = d0 + trow * 2 + d;
        if (dg < n_dst) {
            float* base = aggbuf + ((size_t)b * NN + doff + dg) * DD + col;
            const float4 o0 = make_float4(agg[d][0] * scale, agg[d][1] * scale,
                                          agg[d][2] * scale, agg[d][3] * scale);
            const float4 o1 = make_float4(agg[d][4] * scale, agg[d][5] * scale,
                                          agg[d][6] * scale, agg[d][7] * scale);
            *(float4*)base       = o0;
            *(float4*)(base + 4) = o1;
        }
    }
}

// ---------------------------------------------------------------------------
// self kernel: x_out = relu(x @ Wself + b_self + agg0 + agg1)
// ---------------------------------------------------------------------------
__global__ __launch_bounds__(128) void self_kernel(const float* __restrict__ xin,
                                                   const float* __restrict__ wsl,
                                                   const float* __restrict__ bsl)
{
    __shared__ float xs[16][128];
    const int t    = threadIdx.x;
    const int row0 = blockIdx.x * 16;

    const float* x = (xin != nullptr) ? xin : g_x;

    {
        const float4* src = (const float4*)(x + (size_t)row0 * DD);
        float4* dst = (float4*)&xs[0][0];
        #pragma unroll
        for (int i = 0; i < 4; i++) dst[t + i * 128] = src[t + i * 128];
    }
    __syncthreads();

    float acc[16];
    #pragma unroll
    for (int r = 0; r < 16; r++) acc[r] = 0.f;

    #pragma unroll 4
    for (int k = 0; k < 128; k++) {
        const float w = __ldg(wsl + k * 128 + t);
        #pragma unroll
        for (int r = 0; r < 16; r++) acc[r] += xs[r][k] * w;
    }

    const float bias = bsl[t];
    #pragma unroll
    for (int r = 0; r < 16; r++) {
        const int row = row0 + r;
        const int n   = row % NN;
        float a = 0.f;
        if (n >= 64) {
            const size_t o = (size_t)row * DD + t;
            a = g_agg[o] + g_agg[(size_t)(BB * NN * DD) + o];
        }
        g_x[(size_t)row * DD + t] = fmaxf(acc[r] + bias + a, 0.f);
    }
}

// ---------------------------------------------------------------------------
// head kernel: per batch b -> mean over nodes, 2x relu MLP, final [128x10]
// ---------------------------------------------------------------------------
__global__ __launch_bounds__(128) void head_kernel(const float* __restrict__ w1,
                                                   const float* __restrict__ b1,
                                                   const float* __restrict__ w2,
                                                   const float* __restrict__ b2,
                                                   const float* __restrict__ w3,
                                                   const float* __restrict__ b3,
                                                   float* __restrict__ out)
{
    __shared__ float g[128];
    __shared__ float h[128];
    const int b = blockIdx.x;
    const int t = threadIdx.x;

    // mean over 458 nodes
    float s = 0.f;
    const float* xb = g_x + (size_t)b * NN * DD;
    for (int n = 0; n < NN; n++) s += xb[(size_t)n * DD + t];
    g[t] = s * (1.f / (float)NN);
    __syncthreads();

    // layer 1
    float acc = 0.f;
    #pragma unroll 4
    for (int k = 0; k < 128; k++) acc += g[k] * __ldg(w1 + k * 128 + t);
    h[t] = fmaxf(acc + b1[t], 0.f);
    __syncthreads();

    // layer 2
    acc = 0.f;
    #pragma unroll 4
    for (int k = 0; k < 128; k++) acc += h[k] * __ldg(w2 + k * 128 + t);
    __syncthreads();
    g[t] = fmaxf(acc + b2[t], 0.f);
    __syncthreads();

    // output projection [128 x 10]
    if (t < 10) {
        float o = b3[t];
        for (int k = 0; k < 128; k++) o += g[k] * __ldg(w3 + k * 10 + t);
        out[b * 10 + t] = o;
    }
}

// ---------------------------------------------------------------------------
// launch
// ---------------------------------------------------------------------------
extern "C" void kernel_launch(void* const* d_in, const int* in_sizes, int n_in,
                              void* d_out, int out_size)
{
    (void)in_sizes; (void)n_in; (void)out_size;
    const float* node_features = (const float*)d_in[0];
    const float* edge_attr     = (const float*)d_in[1];
    const float* w_msg         = (const float*)d_in[2];
    const float* b_msg         = (const float*)d_in[3];
    const float* w_self        = (const float*)d_in[4];
    const float* b_self        = (const float*)d_in[5];
    const float* w1            = (const float*)d_in[6];
    const float* b1            = (const float*)d_in[7];
    const float* w2            = (const float*)d_in[8];
    const float* b2            = (const float*)d_in[9];
    const float* w3            = (const float*)d_in[10];
    const float* b3            = (const float*)d_in[11];
    float* out = (float*)d_out;

    const int smem_bytes = EDGE_SMEM_FLOATS * (int)sizeof(float);
    cudaFuncSetAttribute(edge_kernel, cudaFuncAttributeMaxDynamicSharedMemorySize,
                         smem_bytes);

    for (int l = 0; l < 3; l++) {
        const float* xin = (l == 0) ? node_features : nullptr;
        const float* wl  = w_msg  + (size_t)l * 384 * 128;
        const float* bl  = b_msg  + (size_t)l * 128;
        const float* wsl = w_self + (size_t)l * 128 * 128;
        const float* bsl = b_self + (size_t)l * 128;

        uv_kernel<<<458, 128>>>(xin, wl, bl);
        edge_kernel<<<416, 256, smem_bytes>>>(edge_attr, wl);
        self_kernel<<<458, 128>>>(xin, wsl, bsl);
    }
    head_kernel<<<16, 128>>>(w1, b1, w2, b2, w3, b3, out);
}